// round 15
// baseline (speedup 1.0000x reference)
#include <cuda_runtime.h>
#include <cstdint>

// Problem constants (fixed shapes from reference)
#define BB 2
#define TT 2048
#define DD 512
#define HH 8
#define DH 64
#define SCALE 0.125f   // 64^-0.5

// Scratch: Qp[b,q,h,d] (conv folded into query, scale folded), bias dot per (b,q,h)
__device__ float g_Qp[BB * TT * DD];   // 8.4 MB
__device__ float g_bq[BB * TT * HH];

typedef unsigned long long u64;

__device__ __forceinline__ u64 ffma2(u64 a, u64 b, u64 c) {
    u64 d;
    asm("fma.rn.f32x2 %0, %1, %2, %3;" : "=l"(d) : "l"(a), "l"(b), "l"(c));
    return d;
}
__device__ __forceinline__ float2 unpk(u64 a) {
    float2 r;
    asm("mov.b64 {%0,%1}, %2;" : "=f"(r.x), "=f"(r.y) : "l"(a));
    return r;
}
__device__ __forceinline__ u64 pk2(float x) {
    u64 r;
    asm("mov.b64 %0, {%1,%1};" : "=l"(r) : "f"(x));
    return r;
}
__device__ __forceinline__ uint32_t smem_u32(const void* p) {
    uint32_t a;
    asm("{ .reg .u64 t; cvta.to.shared.u64 t, %1; cvt.u32.u64 %0, t; }"
        : "=r"(a) : "l"(p));
    return a;
}
__device__ __forceinline__ void cp16(uint32_t dst, const void* src) {
    asm volatile("cp.async.cg.shared.global [%0], [%1], 16;" :: "r"(dst), "l"(src));
}
#define CP_COMMIT()  asm volatile("cp.async.commit_group;")
#define CP_WAIT(N)   asm volatile("cp.async.wait_group %0;" :: "n"(N))

// ---------------------------------------------------------------------------
// Kernel 1: Qp[row, h*64+d] = SCALE * sum_j query[row, h*64+j] * conv_w[h*64+j, d]
//           bq[row, h]      = SCALE * sum_j query[row, h*64+j] * conv_b[h*64+j]
// ---------------------------------------------------------------------------
#define TQ1 16
__global__ __launch_bounds__(256) void prep_kernel(
    const float* __restrict__ query,
    const float* __restrict__ conv_w,
    const float* __restrict__ conv_b)
{
    __shared__ __align__(16) float q_sh[TQ1][DD];   // 32 KB
    const int q0 = blockIdx.x * TQ1;                // row base in [0, B*T)
    const int t  = threadIdx.x;

    const float4* qg = (const float4*)(query + (size_t)q0 * DD);
    float4* qs = (float4*)&q_sh[0][0];
    #pragma unroll
    for (int i = 0; i < TQ1 * DD / 4 / 256; ++i)    // 8
        qs[t + i * 256] = qg[t + i * 256];
    __syncthreads();

    // bias dot terms (conv_b is zero in this dataset, but keep it general)
    if (t < TQ1 * HH) {                             // 128 threads
        int q = t >> 3, h = t & 7;
        float acc = 0.f;
        #pragma unroll
        for (int j = 0; j < DH; ++j)
            acc += q_sh[q][h * DH + j] * __ldg(conv_b + h * DH + j);
        g_bq[(q0 + q) * HH + h] = SCALE * acc;
    }

    #pragma unroll 1
    for (int cc = 0; cc < 2; ++cc) {
        int c = t + cc * 256;                       // output column 0..511
        int h = c >> 6;
        float W[DH];
        #pragma unroll
        for (int j = 0; j < DH; ++j)
            W[j] = __ldg(conv_w + (h * DH + j) * DH + (c & 63));
        #pragma unroll 1
        for (int q = 0; q < TQ1; ++q) {
            const float4* qr = (const float4*)&q_sh[q][h * DH];
            float acc = 0.f;
            #pragma unroll
            for (int i = 0; i < 16; ++i) {
                float4 v = qr[i];
                acc += W[4*i+0] * v.x + W[4*i+1] * v.y
                     + W[4*i+2] * v.z + W[4*i+3] * v.w;
            }
            g_Qp[(size_t)(q0 + q) * DD + c] = SCALE * acc;
        }
    }
}

// ---------------------------------------------------------------------------
// Kernel 2: fused scores + head-softmax + context, 2 q-rows per warp,
// KJ=2 SINGLE-LOAD chunks: each 2-key chunk loads V from SMEM ONCE (8
// LDS.128), keeps it in 16 live u64 registers through the softmax, and runs
// the context update entirely from registers (phase-B LDS eliminated; 4
// LDS.128 per key vs 8 in the R9 543us baseline). Fits the 128-reg cap:
// qp 32 + ctx 32 + V 32 + temps ~= 120 regs (R5's KJ=8 attempt needed +64
// and rematerialized; KJ=2 is sized to fit).
// Key fold: lane owns key e&1; partial-dot fold via xor-8 (key exchange)
// then xor-16 (d-half fold); 3-shfl h-softmax; 1-shfl weight allgather.
// Lane layout: h = bits[2:0], e = bits[4:3]; lane e owns 16B d-chunks
// c == e (mod 4) of each 64-float V row: conflict-free LDS.128.
// V tiles (64 keys x 64 d) double-buffered in SMEM via cp.async.
// ---------------------------------------------------------------------------
#define TQ 16
#define KT 64
#define NTILES (TT / KT)
__global__ __launch_bounds__(256, 2) void attn_kernel(
    const float* __restrict__ value,
    float* __restrict__ out)
{
    __shared__ __align__(16) float v_sh[2][KT * DH];   // 2 x 16 KB
    const int b  = blockIdx.y;
    const int q0 = blockIdx.x * TQ;
    const int t  = threadIdx.x;
    const int h  = t & 7;           // softmax group (8 heads)
    const int e  = (t >> 3) & 3;    // d-quarter
    const int ql = t >> 5;          // warp id 0..7
    const int rowA = b * TT + q0 + ql;
    const int rowB = rowA + 8;
    const int myk  = e & 1;         // key slot owned after the fold

    // Qp d-chunks (c = 4i+e) for both rows: 8 u64 each
    u64 qpa[8], qpb[8];
    {
        const longlong2* pa_ = (const longlong2*)(g_Qp + (size_t)rowA * DD + h * DH);
        const longlong2* pb_ = (const longlong2*)(g_Qp + (size_t)rowB * DD + h * DH);
        #pragma unroll
        for (int i = 0; i < 4; ++i) {
            longlong2 va = pa_[i * 4 + e];
            longlong2 vb = pb_[i * 4 + e];
            qpa[2*i] = (u64)va.x;  qpa[2*i+1] = (u64)va.y;
            qpb[2*i] = (u64)vb.x;  qpb[2*i+1] = (u64)vb.y;
        }
    }
    const float ebqA = __expf(g_bq[rowA * HH + h]);
    const float ebqB = __expf(g_bq[rowB * HH + h]);

    u64 cta[8], ctb[8];
    #pragma unroll
    for (int i = 0; i < 8; ++i) { cta[i] = 0ULL; ctb[i] = 0ULL; }

    const char* vbase = (const char*)(value + (size_t)b * TT * DH);
    const uint32_t sb[2] = { smem_u32(&v_sh[0][0]), smem_u32(&v_sh[1][0]) };

    // Prologue: stage tile 0 (16 KB: 4 x 16B per thread)
    {
        const char* src = vbase + t * 16;
        #pragma unroll
        for (int i = 0; i < 4; ++i)
            cp16(sb[0] + t * 16 + i * 4096, src + i * 4096);
        CP_COMMIT();
    }

    #pragma unroll 1
    for (int tile = 0; tile < NTILES; ++tile) {
        if (tile + 1 < NTILES) {
            const char* src = vbase + (size_t)(tile + 1) * (KT * DH * 4) + t * 16;
            uint32_t dbuf = sb[(tile + 1) & 1];
            #pragma unroll
            for (int i = 0; i < 4; ++i)
                cp16(dbuf + t * 16 + i * 4096, src + i * 4096);
            CP_COMMIT();
            CP_WAIT(1);
        } else {
            CP_WAIT(0);
        }
        __syncthreads();

        const longlong2* Vs = (const longlong2*)&v_sh[tile & 1][0];

        #pragma unroll 1
        for (int tt0 = 0; tt0 < KT; tt0 += 2) {
            const longlong2* vr0 = Vs + tt0 * 16;
            const longlong2* vr1 = vr0 + 16;

            // ---- Phase A: load V for both keys ONCE; partial dots ----
            u64 v0[8], v1[8];
            u64 a00 = 0ULL, a01 = 0ULL, b00 = 0ULL, b01 = 0ULL;   // key 0
            u64 a10 = 0ULL, a11 = 0ULL, b10 = 0ULL, b11 = 0ULL;   // key 1
            #pragma unroll
            for (int i = 0; i < 4; ++i) {
                longlong2 vq0 = vr0[i * 4 + e];   // conflict-free LDS.128
                v0[2*i] = (u64)vq0.x;  v0[2*i+1] = (u64)vq0.y;
                a00 = ffma2(qpa[2*i],   v0[2*i],   a00);
                a01 = ffma2(qpa[2*i+1], v0[2*i+1], a01);
                b00 = ffma2(qpb[2*i],   v0[2*i],   b00);
                b01 = ffma2(qpb[2*i+1], v0[2*i+1], b01);
            }
            #pragma unroll
            for (int i = 0; i < 4; ++i) {
                longlong2 vq1 = vr1[i * 4 + e];
                v1[2*i] = (u64)vq1.x;  v1[2*i+1] = (u64)vq1.y;
                a10 = ffma2(qpa[2*i],   v1[2*i],   a10);
                a11 = ffma2(qpa[2*i+1], v1[2*i+1], a11);
                b10 = ffma2(qpb[2*i],   v1[2*i],   b10);
                b11 = ffma2(qpb[2*i+1], v1[2*i+1], b11);
            }
            float pa0, pa1, pb0, pb1;
            {
                float2 x0 = unpk(a00), x1 = unpk(a01);
                float2 y0 = unpk(a10), y1 = unpk(a11);
                pa0 = (x0.x + x0.y) + (x1.x + x1.y);
                pa1 = (y0.x + y0.y) + (y1.x + y1.y);
                float2 z0 = unpk(b00), z1 = unpk(b01);
                float2 u0 = unpk(b10), u1 = unpk(b11);
                pb0 = (z0.x + z0.y) + (z1.x + z1.y);
                pb1 = (u0.x + u0.y) + (u1.x + u1.y);
            }

            // ---- Fold: lane keeps key myk=e&1 ----
            // stage 1 (xor 8): exchange the partner's key partials
            float sendA = myk ? pa0 : pa1;
            float sendB = myk ? pb0 : pb1;
            float recvA = __shfl_xor_sync(0xffffffffu, sendA, 8);
            float recvB = __shfl_xor_sync(0xffffffffu, sendB, 8);
            float halfA = (myk ? pa1 : pa0) + recvA;
            float halfB = (myk ? pb1 : pb0) + recvB;
            // stage 2 (xor 16): fold d-halves
            float sA = halfA + __shfl_xor_sync(0xffffffffu, halfA, 16);
            float sB = halfB + __shfl_xor_sync(0xffffffffu, halfB, 16);

            // ---- Softmax over 8 heads for key myk (no max-subtract) ----
            float exA = __expf(sA) * ebqA;
            float exB = __expf(sB) * ebqB;
            float smA = exA, smB = exB;
            smA += __shfl_xor_sync(0xffffffffu, smA, 1);
            smB += __shfl_xor_sync(0xffffffffu, smB, 1);
            smA += __shfl_xor_sync(0xffffffffu, smA, 2);
            smB += __shfl_xor_sync(0xffffffffu, smB, 2);
            smA += __shfl_xor_sync(0xffffffffu, smA, 4);
            smB += __shfl_xor_sync(0xffffffffu, smB, 4);
            float wmyA = __fdividef(exA, smA);
            float wmyB = __fdividef(exB, smB);
            // allgather the other key's weight (partner e^1)
            float wotA = __shfl_xor_sync(0xffffffffu, wmyA, 8);
            float wotB = __shfl_xor_sync(0xffffffffu, wmyB, 8);

            u64 wA0 = pk2(myk ? wotA : wmyA);   // weight of key tt0
            u64 wA1 = pk2(myk ? wmyA : wotA);   // weight of key tt0+1
            u64 wB0 = pk2(myk ? wotB : wmyB);
            u64 wB1 = pk2(myk ? wmyB : wotB);

            // ---- Phase B: context update from LIVE registers (no LDS) ----
            #pragma unroll
            for (int m = 0; m < 8; ++m) {
                cta[m] = ffma2(wA0, v0[m], cta[m]);
                cta[m] = ffma2(wA1, v1[m], cta[m]);
                ctb[m] = ffma2(wB0, v0[m], ctb[m]);
                ctb[m] = ffma2(wB1, v1[m], ctb[m]);
            }
        }
        __syncthreads();   // protect buffer before next prefetch overwrites it
    }

    // out[b, q, h*64 + chunk(4i+e)] for both rows
    longlong2* opA = (longlong2*)(out + (size_t)rowA * DD + h * DH);
    longlong2* opB = (longlong2*)(out + (size_t)rowB * DD + h * DH);
    #pragma unroll
    for (int i = 0; i < 4; ++i) {
        longlong2 va, vb;
        va.x = (long long)cta[2*i];  va.y = (long long)cta[2*i+1];
        vb.x = (long long)ctb[2*i];  vb.y = (long long)ctb[2*i+1];
        opA[i * 4 + e] = va;
        opB[i * 4 + e] = vb;
    }
}

extern "C" void kernel_launch(void* const* d_in, const int* in_sizes, int n_in,
                              void* d_out, int out_size) {
    const float* query  = (const float*)d_in[0];   // [2,2048,512]
    const float* value  = (const float*)d_in[1];   // [2,2048,64]
    const float* conv_w = (const float*)d_in[2];   // [512,64,1]
    const float* conv_b = (const float*)d_in[3];   // [512]
    float* out = (float*)d_out;                    // [2,2048,512]

    prep_kernel<<<BB * TT / TQ1, 256>>>(query, conv_w, conv_b);
    dim3 grid(TT / TQ, BB);
    attn_kernel<<<grid, 256>>>(value, out);
}

// round 17
// speedup vs baseline: 2.4201x; 2.4201x over previous
#include <cuda_runtime.h>
#include <cuda_bf16.h>
#include <cstdint>

#define BB 2
#define TT 2048
#define DD 512
#define HH 8
#define DH 64
#define SCALE 0.125f   // 64^-0.5

// Scratch: Qp[b,q,h,d] (conv folded, scale folded), bias dot per (b,q,h)
__device__ float g_Qp[BB * TT * DD];   // 8.4 MB
__device__ float g_bq[BB * TT * HH];

typedef uint32_t u32;

__device__ __forceinline__ uint32_t smem_u32(const void* p) {
    uint32_t a;
    asm("{ .reg .u64 t; cvta.to.shared.u64 t, %1; cvt.u32.u64 %0, t; }"
        : "=r"(a) : "l"(p));
    return a;
}
__device__ __forceinline__ void cp16(uint32_t dst, const void* src) {
    asm volatile("cp.async.cg.shared.global [%0], [%1], 16;" :: "r"(dst), "l"(src));
}
#define CP_COMMIT()  asm volatile("cp.async.commit_group;")
#define CP_WAIT0()   asm volatile("cp.async.wait_group 0;")

// m16n8k16 bf16 MMA, f32 accum. A row-major, B col-major fragments.
__device__ __forceinline__ void mma16816(float* c, const u32* a, u32 b0, u32 b1) {
    asm volatile(
        "mma.sync.aligned.m16n8k16.row.col.f32.bf16.bf16.f32 "
        "{%0,%1,%2,%3}, {%4,%5,%6,%7}, {%8,%9}, {%0,%1,%2,%3};"
        : "+f"(c[0]), "+f"(c[1]), "+f"(c[2]), "+f"(c[3])
        : "r"(a[0]), "r"(a[1]), "r"(a[2]), "r"(a[3]), "r"(b0), "r"(b1));
}

// Pack two floats (x -> low bf16, y -> high bf16) into hi and residual-lo regs.
__device__ __forceinline__ void splitpack(float x, float y, u32& hi, u32& lo) {
    __nv_bfloat16 xh = __float2bfloat16_rn(x);
    __nv_bfloat16 yh = __float2bfloat16_rn(y);
    float xr = __bfloat162float(xh), yr = __bfloat162float(yh);
    __nv_bfloat16 xl = __float2bfloat16_rn(x - xr);
    __nv_bfloat16 yl = __float2bfloat16_rn(y - yr);
    __nv_bfloat162 h2; h2.x = xh; h2.y = yh;
    __nv_bfloat162 l2; l2.x = xl; l2.y = yl;
    hi = *(u32*)&h2;  lo = *(u32*)&l2;
}
__device__ __forceinline__ u32 ld32s(const __nv_bfloat16* p) {
    return *(const u32*)p;
}

// ---------------------------------------------------------------------------
// Kernel 1: Qp[row, h*64+d] = SCALE * sum_j query[row, h*64+j] * conv_w[h*64+j, d]
//           bq[row, h]      = SCALE * sum_j query[row, h*64+j] * conv_b[h*64+j]
// ---------------------------------------------------------------------------
#define TQ1 16
__global__ __launch_bounds__(256) void prep_kernel(
    const float* __restrict__ query,
    const float* __restrict__ conv_w,
    const float* __restrict__ conv_b)
{
    __shared__ __align__(16) float q_sh[TQ1][DD];   // 32 KB
    const int q0 = blockIdx.x * TQ1;
    const int t  = threadIdx.x;

    const float4* qg = (const float4*)(query + (size_t)q0 * DD);
    float4* qs = (float4*)&q_sh[0][0];
    #pragma unroll
    for (int i = 0; i < TQ1 * DD / 4 / 256; ++i)
        qs[t + i * 256] = qg[t + i * 256];
    __syncthreads();

    if (t < TQ1 * HH) {
        int q = t >> 3, h = t & 7;
        float acc = 0.f;
        #pragma unroll
        for (int j = 0; j < DH; ++j)
            acc += q_sh[q][h * DH + j] * __ldg(conv_b + h * DH + j);
        g_bq[(q0 + q) * HH + h] = SCALE * acc;
    }

    #pragma unroll 1
    for (int cc = 0; cc < 2; ++cc) {
        int c = t + cc * 256;
        int h = c >> 6;
        float W[DH];
        #pragma unroll
        for (int j = 0; j < DH; ++j)
            W[j] = __ldg(conv_w + (h * DH + j) * DH + (c & 63));
        #pragma unroll 1
        for (int q = 0; q < TQ1; ++q) {
            const float4* qr = (const float4*)&q_sh[q][h * DH];
            float acc = 0.f;
            #pragma unroll
            for (int i = 0; i < 16; ++i) {
                float4 v = qr[i];
                acc += W[4*i+0] * v.x + W[4*i+1] * v.y
                     + W[4*i+2] * v.z + W[4*i+3] * v.w;
            }
            g_Qp[(size_t)(q0 + q) * DD + c] = SCALE * acc;
        }
    }
}

// ---------------------------------------------------------------------------
// Kernel 2: tensor-core attention. Block = 256 threads = 8 warps; warp owns
// 16 MMA rows = (2 q) x (8 h), rows r<8 -> (q0, h=r), r>=8 -> (q1, h=r-8).
// Per 16-key step: S = Qp.V^T via 24 m16n8k16 bf16 MMAs (hi/lo split:
// AhiBhi + AhiBlo + AloBhi); softmax over h = exp in C-frag registers +
// 3-shfl reductions over lanes g (h = g = lane>>2); W C-frags ARE the ctx
// A-frags (flash-attn remap) after bf16 split-pack; ctx += W.V via 24 MMAs.
// V staged per 32 keys (cp.async f32, double-buffered) and converted once
// to bf16 hi/lo in BOTH [t][d] and [d][t] layouts for direct B-frag loads.
// ---------------------------------------------------------------------------
#define STG_T 32
#define NSTAGES (TT / STG_T)

__global__ __launch_bounds__(256, 2) void attn_kernel(
    const float* __restrict__ value,
    float* __restrict__ out)
{
    __shared__ __align__(16) float  raw[2][STG_T][DH];        // 16 KB
    __shared__ __align__(4) __nv_bfloat16 Vhi[STG_T][72];     // t-major, pad
    __shared__ __align__(4) __nv_bfloat16 Vlo[STG_T][72];
    __shared__ __align__(4) __nv_bfloat16 VThi[DH][36];       // d-major, pad
    __shared__ __align__(4) __nv_bfloat16 VTlo[DH][36];

    const int b   = blockIdx.y;
    const int tid = threadIdx.x;
    const int wid = tid >> 5;
    const int lane = tid & 31;
    const int g   = lane >> 2;      // 0..7: MMA row-group AND h index
    const int tig = lane & 3;       // 0..3

    const int q0g = blockIdx.x * 16 + wid * 2;   // global q of rows 0..7
    const int q1g = q0g + 1;                     // global q of rows 8..15
    const size_t rowq0 = (size_t)(b * TT + q0g);
    const size_t rowq1 = (size_t)(b * TT + q1g);

    // ---- Load Qp A-fragments (hi/lo split), once ----
    // a0:(g, 2tig..+1)  a1:(g+8 -> q1, ...)  a2:(g, +8)  a3:(q1, +8)
    u32 ahi[4][4], alo[4][4];
    {
        const float* r0 = g_Qp + rowq0 * DD + g * DH;
        const float* r1 = g_Qp + rowq1 * DD + g * DH;
        #pragma unroll
        for (int k = 0; k < 4; ++k) {
            float2 x;
            x = *(const float2*)(r0 + k * 16 + 2 * tig);
            splitpack(x.x, x.y, ahi[k][0], alo[k][0]);
            x = *(const float2*)(r1 + k * 16 + 2 * tig);
            splitpack(x.x, x.y, ahi[k][1], alo[k][1]);
            x = *(const float2*)(r0 + k * 16 + 2 * tig + 8);
            splitpack(x.x, x.y, ahi[k][2], alo[k][2]);
            x = *(const float2*)(r1 + k * 16 + 2 * tig + 8);
            splitpack(x.x, x.y, ahi[k][3], alo[k][3]);
        }
    }
    const float ebq0 = __expf(g_bq[rowq0 * HH + g]);
    const float ebq1 = __expf(g_bq[rowq1 * HH + g]);

    float ctx[8][4];
    #pragma unroll
    for (int dn = 0; dn < 8; ++dn)
        #pragma unroll
        for (int i = 0; i < 4; ++i) ctx[dn][i] = 0.f;

    const char* vsrc = (const char*)(value + (size_t)b * TT * DH);
    const uint32_t rawS[2] = { smem_u32(&raw[0][0][0]), smem_u32(&raw[1][0][0]) };

    // Prefetch stage 0 (8 KB: 2 x 16B per thread)
    cp16(rawS[0] + tid * 16,        vsrc + tid * 16);
    cp16(rawS[0] + tid * 16 + 4096, vsrc + tid * 16 + 4096);
    CP_COMMIT();

    #pragma unroll 1
    for (int stage = 0; stage < NSTAGES; ++stage) {
        CP_WAIT0();
        __syncthreads();   // raw[stage&1] ready; prev MMA reads of bf16 done

        // Prefetch next raw tile (other buffer) -- overlaps convert + MMA
        if (stage + 1 < NSTAGES) {
            const char* src = vsrc + (size_t)(stage + 1) * (STG_T * DH * 4);
            cp16(rawS[(stage + 1) & 1] + tid * 16,        src + tid * 16);
            cp16(rawS[(stage + 1) & 1] + tid * 16 + 4096, src + tid * 16 + 4096);
            CP_COMMIT();
        }

        // Convert raw f32 -> bf16 hi/lo in both layouts. 512 2x2 squares.
        {
            const float (*rw)[DH] = raw[stage & 1];
            #pragma unroll
            for (int s = 0; s < 2; ++s) {
                int sq = tid + s * 256;
                int tp = sq >> 5, dp = sq & 31;
                int tt = tp * 2, dd = dp * 2;
                float x00 = rw[tt][dd],     x01 = rw[tt][dd + 1];
                float x10 = rw[tt + 1][dd], x11 = rw[tt + 1][dd + 1];
                u32 h_, l_;
                splitpack(x00, x01, h_, l_);
                *(u32*)&Vhi[tt][dd] = h_;      *(u32*)&Vlo[tt][dd] = l_;
                splitpack(x10, x11, h_, l_);
                *(u32*)&Vhi[tt + 1][dd] = h_;  *(u32*)&Vlo[tt + 1][dd] = l_;
                splitpack(x00, x10, h_, l_);
                *(u32*)&VThi[dd][tt] = h_;     *(u32*)&VTlo[dd][tt] = l_;
                splitpack(x01, x11, h_, l_);
                *(u32*)&VThi[dd + 1][tt] = h_; *(u32*)&VTlo[dd + 1][tt] = l_;
            }
        }
        __syncthreads();   // bf16 tiles ready

        #pragma unroll
        for (int sub = 0; sub < 2; ++sub) {
            const int tl = sub * 16;   // key base within the 32-key stage

            // ---- Score: S[16 rows x 16 keys] ----
            float cs[2][4];
            #pragma unroll
            for (int i = 0; i < 4; ++i) { cs[0][i] = 0.f; cs[1][i] = 0.f; }
            #pragma unroll
            for (int k = 0; k < 4; ++k) {
                #pragma unroll
                for (int tile = 0; tile < 2; ++tile) {
                    const __nv_bfloat16* ph = &Vhi[tl + tile * 8 + g][k * 16 + 2 * tig];
                    const __nv_bfloat16* pl = &Vlo[tl + tile * 8 + g][k * 16 + 2 * tig];
                    u32 bh0 = ld32s(ph), bh1 = ld32s(ph + 8);
                    u32 bl0 = ld32s(pl), bl1 = ld32s(pl + 8);
                    mma16816(cs[tile], ahi[k], bh0, bh1);
                    mma16816(cs[tile], ahi[k], bl0, bl1);
                    mma16816(cs[tile], alo[k], bh0, bh1);
                }
            }

            // ---- Softmax over h (rows within q): reduce over lanes g ----
            u32 wahi[4], walo[4];
            #pragma unroll
            for (int tile = 0; tile < 2; ++tile) {
                float e0 = __expf(cs[tile][0]) * ebq0;
                float e1 = __expf(cs[tile][1]) * ebq0;
                float e2 = __expf(cs[tile][2]) * ebq1;
                float e3 = __expf(cs[tile][3]) * ebq1;
                float s0 = e0, s1 = e1, s2 = e2, s3 = e3;
                #pragma unroll
                for (int m = 4; m <= 16; m <<= 1) {
                    s0 += __shfl_xor_sync(0xffffffffu, s0, m);
                    s1 += __shfl_xor_sync(0xffffffffu, s1, m);
                    s2 += __shfl_xor_sync(0xffffffffu, s2, m);
                    s3 += __shfl_xor_sync(0xffffffffu, s3, m);
                }
                float w0 = __fdividef(e0, s0), w1 = __fdividef(e1, s1);
                float w2 = __fdividef(e2, s2), w3 = __fdividef(e3, s3);
                splitpack(w0, w1, wahi[tile * 2 + 0], walo[tile * 2 + 0]);
                splitpack(w2, w3, wahi[tile * 2 + 1], walo[tile * 2 + 1]);
            }

            // ---- Context: ctx += W . V  (K = 16 keys, N = 64 d) ----
            #pragma unroll
            for (int dn = 0; dn < 8; ++dn) {
                const __nv_bfloat16* ph = &VThi[dn * 8 + g][tl + 2 * tig];
                const __nv_bfloat16* pl = &VTlo[dn * 8 + g][tl + 2 * tig];
                u32 bh0 = ld32s(ph), bh1 = ld32s(ph + 8);
                u32 bl0 = ld32s(pl), bl1 = ld32s(pl + 8);
                mma16816(ctx[dn], wahi, bh0, bh1);
                mma16816(ctx[dn], wahi, bl0, bl1);
                mma16816(ctx[dn], walo, bh0, bh1);
            }
        }
    }

    // ---- Store: c0,c1 -> (q0, h=g, d=dn*8+2tig..+1); c2,c3 -> q1 ----
    float* o0 = out + rowq0 * DD + g * DH + 2 * tig;
    float* o1 = out + rowq1 * DD + g * DH + 2 * tig;
    #pragma unroll
    for (int dn = 0; dn < 8; ++dn) {
        float2 v0; v0.x = ctx[dn][0]; v0.y = ctx[dn][1];
        float2 v1; v1.x = ctx[dn][2]; v1.y = ctx[dn][3];
        *(float2*)(o0 + dn * 8) = v0;
        *(float2*)(o1 + dn * 8) = v1;
    }
}

extern "C" void kernel_launch(void* const* d_in, const int* in_sizes, int n_in,
                              void* d_out, int out_size) {
    const float* query  = (const float*)d_in[0];   // [2,2048,512]
    const float* value  = (const float*)d_in[1];   // [2,2048,64]
    const float* conv_w = (const float*)d_in[2];   // [512,64,1]
    const float* conv_b = (const float*)d_in[3];   // [512]
    float* out = (float*)d_out;                    // [2,2048,512]

    prep_kernel<<<BB * TT / TQ1, 256>>>(query, conv_w, conv_b);
    dim3 grid(TT / 16, BB);
    attn_kernel<<<grid, 256>>>(value, out);
}